// round 1
// baseline (speedup 1.0000x reference)
#include <cuda_runtime.h>
#include <math.h>
#include <math_constants.h>

// LocalHolder2D: out = sum_i w_i * log10(maxpool_k(x)), k = 3,5,7
// x: (B=8, C=64, H=256, W=256) fp32, strictly positive.
// w_i = (log10(k_i) - mean) / sum((log10(k_j)-mean)^2); sum w_i = 0, the
// log10(k/(H*W)) offset cancels under centering.

#define HH 256
#define WW 256
#define ROWS_PER_BLOCK 64
#define WARPS_PER_BLOCK 10
#define COLS_PER_WARP 26
#define THREADS (WARPS_PER_BLOCK * 32)

__global__ __launch_bounds__(THREADS, 4)
void holder_kernel(const float* __restrict__ x, float* __restrict__ out,
                   float w3, float w5, float w7)
{
    const int warp = threadIdx.x >> 5;
    const int lane = threadIdx.x & 31;
    // warp w produces output columns [26w .. 26w+25]; lanes carry +-3 halo
    const int c = warp * COLS_PER_WARP + lane - 3;

    const int chunk = blockIdx.x & 3;          // 4 chunks of 64 rows
    const int plane = blockIdx.x >> 2;
    const int y0 = chunk * ROWS_PER_BLOCK;

    const float* __restrict__ src = x  + (size_t)plane * (HH * WW);
    float*       __restrict__ dst = out + (size_t)plane * (HH * WW);

    const bool cvalid = (c >= 0) & (c < WW);
    const bool ovalid = (lane >= 3) & (lane <= 28) & (c < WW);  // c>=0 implied by lane>=3

    const float NEG = -CUDART_INF_F;

    // Ring buffer of 8 input rows for this thread's column.
    // Slot written at (virtual) iteration i holds input row y0+i+3.
    float r[8];

    // Prologue: virtual iterations i = -6..-1 fill slots (i&7) = 2..7 with
    // rows y0-3 .. y0+2 (rows < 0 are -inf padding).
    #pragma unroll
    for (int j = 0; j < 6; ++j) {
        int row = y0 - 3 + j;
        bool v = cvalid & (row >= 0);
        r[2 + j] = v ? src[row * WW + c] : NEG;
    }

    for (int ib = 0; ib < ROWS_PER_BLOCK; ib += 8) {
        #pragma unroll
        for (int u = 0; u < 8; ++u) {
            const int i = ib + u;          // i & 7 == u (ib multiple of 8)
            const int y = y0 + i;          // output row
            // Load row y+3 into slot u
            {
                int rowin = y + 3;
                bool v = cvalid & (rowin < HH);
                r[u] = v ? src[rowin * WW + c] : NEG;
            }
            // Vertical maxes along this column.
            // Row y+3-k lives in slot (u-k)&7.
            const float rm1 = r[(u + 4) & 7];  // y-1
            const float r0  = r[(u + 5) & 7];  // y
            const float rp1 = r[(u + 6) & 7];  // y+1
            const float rm2 = r[(u + 3) & 7];  // y-2
            const float rp2 = r[(u + 7) & 7];  // y+2
            const float rm3 = r[(u + 2) & 7];  // y-3
            const float rp3 = r[ u         ];  // y+3

            float v3 = fmaxf(fmaxf(rm1, r0), rp1);
            float v5 = fmaxf(v3, fmaxf(rm2, rp2));
            float v7 = fmaxf(v5, fmaxf(rm3, rp3));

            // Horizontal maxes via warp shuffles (halo lanes make edges safe
            // for output lanes 3..28).
            // m3: +-1
            float m3 = fmaxf(v3,
                        fmaxf(__shfl_up_sync(0xffffffffu, v3, 1),
                              __shfl_down_sync(0xffffffffu, v3, 1)));
            // m5: +-2  (a5[x] = max v5[x..x+1])
            float a5 = fmaxf(v5, __shfl_down_sync(0xffffffffu, v5, 1));
            float m5 = fmaxf(fmaxf(a5, __shfl_up_sync(0xffffffffu, a5, 2)),
                             __shfl_down_sync(0xffffffffu, v5, 2));
            // m7: +-3  (a7=[x..x+1], b7=[x..x+3], m7 = max(b7, b7[x-3]))
            float a7 = fmaxf(v7, __shfl_down_sync(0xffffffffu, v7, 1));
            float b7 = fmaxf(a7, __shfl_down_sync(0xffffffffu, a7, 2));
            float m7 = fmaxf(b7, __shfl_up_sync(0xffffffffu, b7, 3));

            if (ovalid) {
                float val = w3 * __log2f(m3)
                          + w5 * __log2f(m5)
                          + w7 * __log2f(m7);
                dst[y * WW + c] = val;
            }
        }
    }
}

extern "C" void kernel_launch(void* const* d_in, const int* in_sizes, int n_in,
                              void* d_out, int out_size)
{
    const float* x = (const float*)d_in[0];
    float* out = (float*)d_out;

    const int planes = in_sizes[0] / (HH * WW);   // B*C = 512

    // Closed-form OLS slope weights, double precision on host.
    double l3 = log10(3.0), l5 = log10(5.0), l7 = log10(7.0);
    double mean = (l3 + l5 + l7) / 3.0;
    double c3 = l3 - mean, c5 = l5 - mean, c7 = l7 - mean;
    double s = c3 * c3 + c5 * c5 + c7 * c7;
    // fold log10(m) = log2(m) * log10(2) into the weights
    double L10_2 = 0.30102999566398119521;
    float w3 = (float)((c3 / s) * L10_2);
    float w5 = (float)((c5 / s) * L10_2);
    float w7 = (float)((c7 / s) * L10_2);

    dim3 grid(planes * 4);
    dim3 block(THREADS);
    holder_kernel<<<grid, block>>>(x, out, w3, w5, w7);
}

// round 2
// speedup vs baseline: 1.3053x; 1.3053x over previous
#include <cuda_runtime.h>
#include <math.h>
#include <math_constants.h>

// LocalHolder2D: out = sum_i w_i * log10(maxpool_k(x)), k = 3,5,7
// x: (B=8, C=64, H=256, W=256) fp32, strictly positive.
// Weights centered (sum w_i = 0) so the log10(1/(H*W)) offset cancels.
//
// Strategy: 2 columns per thread (float2), vertical max in a register ring
// (slot = row & 7, prefetch +4 rows ahead), horizontal max via warp shuffles
// of per-thread pair maxes. Zero shared memory, zero __syncthreads.

#define HH 256
#define WW 256
#define ROWS_PER_BLOCK 32
#define WARPS_PER_BLOCK 5
#define OUTCOLS_PER_WARP 56   /* 28 active threads x 2 cols, 2 halo threads/side */
#define THREADS (WARPS_PER_BLOCK * 32)

__global__ __launch_bounds__(THREADS, 6)
void holder_kernel(const float* __restrict__ x, float* __restrict__ out,
                   float w3, float w5, float w7)
{
    const int warp = threadIdx.x >> 5;
    const int lane = threadIdx.x & 31;
    // thread covers columns c, c+1 (c even); lanes 0,1 / 30,31 are halo
    const int c = warp * OUTCOLS_PER_WARP + lane * 2 - 4;

    const int chunk = blockIdx.x & 7;          // 8 chunks of 32 rows
    const int plane = blockIdx.x >> 3;
    const int y0 = chunk * ROWS_PER_BLOCK;

    const float* __restrict__ src = x   + (size_t)plane * (HH * WW);
    float*       __restrict__ dst = out + (size_t)plane * (HH * WW);

    const bool cvalid = (c >= 0) & (c < WW);
    const bool ovalid = (lane >= 2) & (lane <= 29) & (c < WW);

    const float NEG = -CUDART_INF_F;
    const unsigned FULL = 0xffffffffu;

    // Ring of 8 rows (float2 each); slot for row r is (r & 7).
    // Invariant entering output row y: rows y-3 .. y+3 resident.
    float2 r[8];

    // Prologue: rows y0-3 .. y0+3  (y0 % 8 == 0 -> slots 5,6,7,0,1,2,3)
    #pragma unroll
    for (int j = 0; j < 7; ++j) {
        int row = y0 - 3 + j;
        bool v = cvalid & (row >= 0);
        float2 t;
        if (v) t = *(const float2*)(src + row * WW + c);
        else   t = make_float2(NEG, NEG);
        r[(row + 8) & 7] = t;
    }

    for (int ib = 0; ib < ROWS_PER_BLOCK; ib += 8) {
        #pragma unroll
        for (int u = 0; u < 8; ++u) {
            const int y = y0 + ib + u;     // output row; y & 7 == u
            // Prefetch row y+4 into slot (u+4)&7 (vacated row y-4).
            {
                int rowin = y + 4;
                bool v = cvalid & (rowin < HH);
                float2 t;
                if (v) t = *(const float2*)(src + rowin * WW + c);
                else   t = make_float2(NEG, NEG);
                r[(u + 4) & 7] = t;
            }
            const float2 rm3 = r[(u + 5) & 7];
            const float2 rm2 = r[(u + 6) & 7];
            const float2 rm1 = r[(u + 7) & 7];
            const float2 r0  = r[ u         ];
            const float2 rp1 = r[(u + 1) & 7];
            const float2 rp2 = r[(u + 2) & 7];
            const float2 rp3 = r[(u + 3) & 7];

            // Vertical maxes (per column)
            float v3x = fmaxf(fmaxf(rm1.x, r0.x), rp1.x);
            float v3y = fmaxf(fmaxf(rm1.y, r0.y), rp1.y);
            float v5x = fmaxf(v3x, fmaxf(rm2.x, rp2.x));
            float v5y = fmaxf(v3y, fmaxf(rm2.y, rp2.y));
            float v7x = fmaxf(v5x, fmaxf(rm3.x, rp3.x));
            float v7y = fmaxf(v5y, fmaxf(rm3.y, rp3.y));

            // Per-thread pair maxes (cols c..c+1)
            float p3 = fmaxf(v3x, v3y);
            float p5 = fmaxf(v5x, v5y);
            float p7 = fmaxf(v7x, v7y);

            // k=3: m[c]   = max(x[c-1], p3)
            //      m[c+1] = max(p3, x[c+2])
            float e3m = __shfl_up_sync  (FULL, v3y, 1);   // col c-1
            float e3p = __shfl_down_sync(FULL, v3x, 1);   // col c+2
            float m3lo = fmaxf(e3m, p3);
            float m3hi = fmaxf(p3, e3p);

            // k=5: m[c]   = max(p5[t-1], p5, x[c+2])
            //      m[c+1] = max(x[c-1], p5, p5[t+1])
            float p5m = __shfl_up_sync  (FULL, p5, 1);
            float p5p = __shfl_down_sync(FULL, p5, 1);
            float e5m = __shfl_up_sync  (FULL, v5y, 1);   // col c-1
            float e5p = __shfl_down_sync(FULL, v5x, 1);   // col c+2
            float m5lo = fmaxf(fmaxf(p5m, p5), e5p);
            float m5hi = fmaxf(fmaxf(e5m, p5), p5p);

            // k=7: q7 = max over cols c-2..c+3
            //      m[c]   = max(x[c-3], q7)
            //      m[c+1] = max(q7, x[c+4])
            float p7m = __shfl_up_sync  (FULL, p7, 1);
            float p7p = __shfl_down_sync(FULL, p7, 1);
            float e7m = __shfl_up_sync  (FULL, v7y, 2);   // col c-3
            float e7p = __shfl_down_sync(FULL, v7x, 2);   // col c+4
            float q7  = fmaxf(fmaxf(p7m, p7), p7p);
            float m7lo = fmaxf(e7m, q7);
            float m7hi = fmaxf(q7, e7p);

            if (ovalid) {
                float lo = fmaf(w3, __log2f(m3lo),
                           fmaf(w5, __log2f(m5lo), w7 * __log2f(m7lo)));
                float hi = fmaf(w3, __log2f(m3hi),
                           fmaf(w5, __log2f(m5hi), w7 * __log2f(m7hi)));
                *(float2*)(dst + y * WW + c) = make_float2(lo, hi);
            }
        }
    }
}

extern "C" void kernel_launch(void* const* d_in, const int* in_sizes, int n_in,
                              void* d_out, int out_size)
{
    const float* x = (const float*)d_in[0];
    float* out = (float*)d_out;

    const int planes = in_sizes[0] / (HH * WW);   // B*C = 512

    // Closed-form OLS slope weights (double on host); fold in log10(2)
    // so device uses log2.
    double l3 = log10(3.0), l5 = log10(5.0), l7 = log10(7.0);
    double mean = (l3 + l5 + l7) / 3.0;
    double c3 = l3 - mean, c5 = l5 - mean, c7 = l7 - mean;
    double s = c3 * c3 + c5 * c5 + c7 * c7;
    double L10_2 = 0.30102999566398119521;
    float w3 = (float)((c3 / s) * L10_2);
    float w5 = (float)((c5 / s) * L10_2);
    float w7 = (float)((c7 / s) * L10_2);

    dim3 grid(planes * (HH / ROWS_PER_BLOCK));
    dim3 block(THREADS);
    holder_kernel<<<grid, block>>>(x, out, w3, w5, w7);
}

// round 3
// speedup vs baseline: 1.3250x; 1.0151x over previous
#include <cuda_runtime.h>
#include <math.h>
#include <math_constants.h>

// LocalHolder2D: out = sum_i w_i * log10(maxpool_k(x)), k = 3,5,7
// x: (B=8, C=64, H=256, W=256) fp32, strictly positive.
// Weights centered (sum w_i = 0) so the log10(1/(H*W)) offset cancels.
//
// Key trick this revision: all inputs are > 0 (padding -inf), so IEEE fp32
// bit patterns are monotone under SIGNED integer comparison. The entire
// max-pool tree runs in the integer domain using the 3-input
// __vimax3_s32 (one VIMNMX3 per 3-way max) — ~18% fewer issue slots.
//
// Layout: 2 columns per thread (int2 ring of 8 rows, slot = row & 7,
// prefetch +4 rows), horizontal max via warp shuffles. No smem, no syncs.

#define HH 256
#define WW 256
#define ROWS_PER_BLOCK 32
#define WARPS_PER_BLOCK 5
#define OUTCOLS_PER_WARP 56   /* 28 active threads x 2 cols, 2 halo threads/side */
#define THREADS (WARPS_PER_BLOCK * 32)

// -inf as signed int bits: smaller than any positive float's bits.
#define NEG_I ((int)0xff800000)

static __device__ __forceinline__ int imax2(int a, int b) { return a > b ? a : b; }

__global__ __launch_bounds__(THREADS, 6)
void holder_kernel(const int* __restrict__ x, float* __restrict__ out,
                   float w3, float w5, float w7)
{
    const int warp = threadIdx.x >> 5;
    const int lane = threadIdx.x & 31;
    // thread covers columns c, c+1 (c even); lanes 0,1 / 30,31 are halo
    const int c = warp * OUTCOLS_PER_WARP + lane * 2 - 4;

    const int chunk = blockIdx.x & 7;          // 8 chunks of 32 rows
    const int plane = blockIdx.x >> 3;
    const int y0 = chunk * ROWS_PER_BLOCK;

    const int*  __restrict__ src = x   + (size_t)plane * (HH * WW);
    float*      __restrict__ dst = out + (size_t)plane * (HH * WW);

    const bool cvalid = (c >= 0) & (c < WW);
    const bool ovalid = (lane >= 2) & (lane <= 29) & (c < WW);

    const unsigned FULL = 0xffffffffu;

    // Ring of 8 rows (int2 each); slot for row r is (r & 7).
    // Invariant entering output row y: rows y-3 .. y+3 resident.
    int2 r[8];

    // Prologue: rows y0-3 .. y0+3
    #pragma unroll
    for (int j = 0; j < 7; ++j) {
        int row = y0 - 3 + j;
        bool v = cvalid & (row >= 0);
        int2 t;
        if (v) t = *(const int2*)(src + row * WW + c);
        else   t = make_int2(NEG_I, NEG_I);
        r[(row + 8) & 7] = t;
    }

    for (int ib = 0; ib < ROWS_PER_BLOCK; ib += 8) {
        #pragma unroll
        for (int u = 0; u < 8; ++u) {
            const int y = y0 + ib + u;     // output row; y & 7 == u
            // Prefetch row y+4 into slot (u+4)&7 (vacated row y-4).
            {
                int rowin = y + 4;
                bool v = cvalid & (rowin < HH);
                int2 t;
                if (v) t = *(const int2*)(src + rowin * WW + c);
                else   t = make_int2(NEG_I, NEG_I);
                r[(u + 4) & 7] = t;
            }
            const int2 rm3 = r[(u + 5) & 7];
            const int2 rm2 = r[(u + 6) & 7];
            const int2 rm1 = r[(u + 7) & 7];
            const int2 r0  = r[ u         ];
            const int2 rp1 = r[(u + 1) & 7];
            const int2 rp2 = r[(u + 2) & 7];
            const int2 rp3 = r[(u + 3) & 7];

            // Vertical maxes (per column), one VIMNMX3 per window growth.
            int v3x = __vimax3_s32(rm1.x, r0.x, rp1.x);
            int v3y = __vimax3_s32(rm1.y, r0.y, rp1.y);
            int v5x = __vimax3_s32(v3x, rm2.x, rp2.x);
            int v5y = __vimax3_s32(v3y, rm2.y, rp2.y);
            int v7x = __vimax3_s32(v5x, rm3.x, rp3.x);
            int v7y = __vimax3_s32(v5y, rm3.y, rp3.y);

            // k=3: m[c]   = max(x[c-1], v3x, v3y)
            //      m[c+1] = max(v3x, v3y, x[c+2])
            int e3m = __shfl_up_sync  (FULL, v3y, 1);   // col c-1
            int e3p = __shfl_down_sync(FULL, v3x, 1);   // col c+2
            int m3lo = __vimax3_s32(e3m, v3x, v3y);
            int m3hi = __vimax3_s32(v3x, v3y, e3p);

            // k=5: p5 = max over cols c..c+1
            //      m[c]   = max(p5[t-1], p5, x[c+2])
            //      m[c+1] = max(x[c-1], p5, p5[t+1])
            int p5  = imax2(v5x, v5y);
            int p5m = __shfl_up_sync  (FULL, p5, 1);
            int p5p = __shfl_down_sync(FULL, p5, 1);
            int e5m = __shfl_up_sync  (FULL, v5y, 1);   // col c-1
            int e5p = __shfl_down_sync(FULL, v5x, 1);   // col c+2
            int m5lo = __vimax3_s32(p5m, p5, e5p);
            int m5hi = __vimax3_s32(e5m, p5, p5p);

            // k=7: q7a = max over cols c-2..c+3
            //      m[c]   = max(x[c-3], q7a)
            //      m[c+1] = max(q7a, x[c+4])
            int p7  = imax2(v7x, v7y);
            int p7m = __shfl_up_sync  (FULL, p7, 1);
            int p7p = __shfl_down_sync(FULL, p7, 1);
            int e7m = __shfl_up_sync  (FULL, v7y, 2);   // col c-3
            int e7p = __shfl_down_sync(FULL, v7x, 2);   // col c+4
            int q7a = __vimax3_s32(p7m, p7, p7p);
            int m7lo = imax2(e7m, q7a);
            int m7hi = imax2(q7a, e7p);

            if (ovalid) {
                float lo = fmaf(w3, __log2f(__int_as_float(m3lo)),
                           fmaf(w5, __log2f(__int_as_float(m5lo)),
                                w7 * __log2f(__int_as_float(m7lo))));
                float hi = fmaf(w3, __log2f(__int_as_float(m3hi)),
                           fmaf(w5, __log2f(__int_as_float(m5hi)),
                                w7 * __log2f(__int_as_float(m7hi))));
                *(float2*)(dst + y * WW + c) = make_float2(lo, hi);
            }
        }
    }
}

extern "C" void kernel_launch(void* const* d_in, const int* in_sizes, int n_in,
                              void* d_out, int out_size)
{
    const int* x = (const int*)d_in[0];
    float* out = (float*)d_out;

    const int planes = in_sizes[0] / (HH * WW);   // B*C = 512

    // Closed-form OLS slope weights (double on host); fold in log10(2)
    // so device uses log2.
    double l3 = log10(3.0), l5 = log10(5.0), l7 = log10(7.0);
    double mean = (l3 + l5 + l7) / 3.0;
    double c3 = l3 - mean, c5 = l5 - mean, c7 = l7 - mean;
    double s = c3 * c3 + c5 * c5 + c7 * c7;
    double L10_2 = 0.30102999566398119521;
    float w3 = (float)((c3 / s) * L10_2);
    float w5 = (float)((c5 / s) * L10_2);
    float w7 = (float)((c7 / s) * L10_2);

    dim3 grid(planes * (HH / ROWS_PER_BLOCK));
    dim3 block(THREADS);
    holder_kernel<<<grid, block>>>(x, out, w3, w5, w7);
}

// round 5
// speedup vs baseline: 1.5507x; 1.1704x over previous
#include <cuda_runtime.h>
#include <math.h>

// LocalHolder2D: out = sum_i w_i * log10(maxpool_k(x)), k = 3,5,7
// x: (B=8, C=64, H=256, W=256) fp32, strictly positive.
// Centered OLS weights (sum w_i = 0) -> the log10(1/(H*W)) offset cancels.
//
// R4 design: ONE FULL ROW PER WARP. 32 lanes x 8 cols = 256 = W, so there
// are no halo lanes at all; image edges are -inf via SEL on lanes 0/31.
// Max tree in signed-int domain (positive floats + -inf are monotone under
// signed int compare), using 3-input VIMNMX3. Horizontal windows factor
// through per-thread pair/quad maxes; only 12 shuffles per 8 outputs.
// Vertical pass: register ring of 8 rows x 8 cols (slot = row & 7),
// prefetch +4 rows ahead. No shared memory, no syncs.

#define HH 256
#define WW 256
#define RPB 64                 /* rows per warp-task; 6/64 = 9.4% reload halo */
#define WARPS 4
#define THREADS (WARPS * 32)
#define NEG_I ((int)0xff800000)   /* -inf bits */

static __device__ __forceinline__ int imax2(int a, int b) { return a > b ? a : b; }

__global__ __launch_bounds__(THREADS, 4)
void holder_kernel(const int* __restrict__ x, float* __restrict__ out,
                   float w3, float w5, float w7)
{
    const int lane = threadIdx.x & 31;
    const int warp = threadIdx.x >> 5;
    const int task = blockIdx.x * WARPS + warp;     // 2048 tasks
    const int plane = task >> 2;
    const int y0 = (task & 3) * RPB;                // multiple of 8

    const int* __restrict__ src = x   + (size_t)plane * (HH * WW) + lane * 8;
    float*     __restrict__ dst = out + (size_t)plane * (HH * WW) + lane * 8;

    const unsigned FULL = 0xffffffffu;
    const bool l0 = (lane == 0), l31 = (lane == 31);

    // ring[slot][col]; slot for row r is r & 7 (y0 % 8 == 0).
    int ring[8][8];

    // Prologue: rows y0-3 .. y0+3 -> slots (j+5)&7 for j=0..6.
    #pragma unroll
    for (int j = 0; j < 7; ++j) {
        const int row = y0 - 3 + j;
        const int s = (j + 5) & 7;
        if (row >= 0) {
            const int4* rp = (const int4*)(src + row * WW);
            int4 a = rp[0], b = rp[1];
            ring[s][0] = a.x; ring[s][1] = a.y; ring[s][2] = a.z; ring[s][3] = a.w;
            ring[s][4] = b.x; ring[s][5] = b.y; ring[s][6] = b.z; ring[s][7] = b.w;
        } else {
            #pragma unroll
            for (int t = 0; t < 8; ++t) ring[s][t] = NEG_I;
        }
    }

    for (int ib = 0; ib < RPB; ib += 8) {
        #pragma unroll
        for (int u = 0; u < 8; ++u) {
            const int y = y0 + ib + u;            // output row; y & 7 == u
            // Prefetch row y+4 into slot (u+4)&7.
            {
                const int row = y + 4;
                const int s = (u + 4) & 7;
                if (row < HH) {
                    const int4* rp = (const int4*)(src + row * WW);
                    int4 a = rp[0], b = rp[1];
                    ring[s][0] = a.x; ring[s][1] = a.y; ring[s][2] = a.z; ring[s][3] = a.w;
                    ring[s][4] = b.x; ring[s][5] = b.y; ring[s][6] = b.z; ring[s][7] = b.w;
                } else {
                    #pragma unroll
                    for (int t = 0; t < 8; ++t) ring[s][t] = NEG_I;
                }
            }

            int v[8];
            float acc[8];

            // ---- k = 3 ----
            #pragma unroll
            for (int j = 0; j < 8; ++j)
                v[j] = __vimax3_s32(ring[(u + 7) & 7][j], ring[u][j],
                                    ring[(u + 1) & 7][j]);
            {
                int L = __shfl_up_sync  (FULL, v[7], 1); if (l0)  L = NEG_I;
                int R = __shfl_down_sync(FULL, v[0], 1); if (l31) R = NEG_I;
                int m0 = __vimax3_s32(L, v[0], v[1]);
                int m7 = __vimax3_s32(v[6], v[7], R);
                acc[0] = w3 * __log2f(__int_as_float(m0));
                #pragma unroll
                for (int j = 1; j < 7; ++j)
                    acc[j] = w3 * __log2f(__int_as_float(
                                 __vimax3_s32(v[j - 1], v[j], v[j + 1])));
                acc[7] = w3 * __log2f(__int_as_float(m7));
            }

            // ---- k = 5 ----
            #pragma unroll
            for (int j = 0; j < 8; ++j)
                v[j] = __vimax3_s32(v[j], ring[(u + 6) & 7][j],
                                    ring[(u + 2) & 7][j]);
            {
                int p01 = imax2(v[0], v[1]), p23 = imax2(v[2], v[3]);
                int p45 = imax2(v[4], v[5]), p67 = imax2(v[6], v[7]);
                int Lp = __shfl_up_sync  (FULL, p67, 1);
                int L7 = __shfl_up_sync  (FULL, v[7], 1);
                int R0 = __shfl_down_sync(FULL, v[0], 1);
                int Rp = __shfl_down_sync(FULL, p01, 1);
                if (l0)  { Lp = NEG_I; L7 = NEG_I; }
                if (l31) { R0 = NEG_I; Rp = NEG_I; }
                int m[8];
                m[0] = __vimax3_s32(Lp,  p01, v[2]);
                m[1] = __vimax3_s32(L7,  p01, p23);
                m[2] = __vimax3_s32(p01, p23, v[4]);
                m[3] = __vimax3_s32(v[1], p23, p45);
                m[4] = __vimax3_s32(p23, p45, v[6]);
                m[5] = __vimax3_s32(v[3], p45, p67);
                m[6] = __vimax3_s32(p45, p67, R0);
                m[7] = __vimax3_s32(v[5], p67, Rp);
                #pragma unroll
                for (int j = 0; j < 8; ++j)
                    acc[j] = fmaf(w5, __log2f(__int_as_float(m[j])), acc[j]);
            }

            // ---- k = 7 ----
            #pragma unroll
            for (int j = 0; j < 8; ++j)
                v[j] = __vimax3_s32(v[j], ring[(u + 5) & 7][j],
                                    ring[(u + 3) & 7][j]);
            {
                int p01 = imax2(v[0], v[1]), p23 = imax2(v[2], v[3]);
                int p45 = imax2(v[4], v[5]), p67 = imax2(v[6], v[7]);
                int a03 = imax2(p01, p23),   a47 = imax2(p45, p67);
                int suf3 = imax2(v[5], p67); // cols 5..7
                int pre3 = imax2(p01, v[2]); // cols 0..2
                int Ls  = __shfl_up_sync  (FULL, suf3, 1);
                int Lq  = __shfl_up_sync  (FULL, p67, 1);
                int L7v = __shfl_up_sync  (FULL, v[7], 1);
                int R0v = __shfl_down_sync(FULL, v[0], 1);
                int Rq  = __shfl_down_sync(FULL, p01, 1);
                int Rp3 = __shfl_down_sync(FULL, pre3, 1);
                if (l0)  { Ls = NEG_I; Lq = NEG_I; L7v = NEG_I; }
                if (l31) { R0v = NEG_I; Rq = NEG_I; Rp3 = NEG_I; }
                int m[8];
                m[0] = imax2(Ls, a03);               // -3..3
                m[1] = __vimax3_s32(Lq,  a03, v[4]); // -2..4
                m[2] = __vimax3_s32(L7v, a03, p45);  // -1..5
                m[3] = __vimax3_s32(a03, p45, v[6]); //  0..6
                m[4] = __vimax3_s32(v[1], p23, a47); //  1..7
                m[5] = __vimax3_s32(p23, a47, R0v);  //  2..8
                m[6] = __vimax3_s32(v[3], a47, Rq);  //  3..9
                m[7] = imax2(a47, Rp3);              //  4..10
                #pragma unroll
                for (int j = 0; j < 8; ++j)
                    acc[j] = fmaf(w7, __log2f(__int_as_float(m[j])), acc[j]);
            }

            float* dp = dst + y * WW;
            ((float4*)dp)[0] = make_float4(acc[0], acc[1], acc[2], acc[3]);
            ((float4*)dp)[1] = make_float4(acc[4], acc[5], acc[6], acc[7]);
        }
    }
}

extern "C" void kernel_launch(void* const* d_in, const int* in_sizes, int n_in,
                              void* d_out, int out_size)
{
    const int* x = (const int*)d_in[0];
    float* out = (float*)d_out;

    const int planes = in_sizes[0] / (HH * WW);     // 512

    // Closed-form OLS slope weights (double on host); fold in log10(2).
    double l3 = log10(3.0), l5 = log10(5.0), l7 = log10(7.0);
    double mean = (l3 + l5 + l7) / 3.0;
    double c3 = l3 - mean, c5 = l5 - mean, c7 = l7 - mean;
    double s = c3 * c3 + c5 * c5 + c7 * c7;
    double L10_2 = 0.30102999566398119521;
    float w3 = (float)((c3 / s) * L10_2);
    float w5 = (float)((c5 / s) * L10_2);
    float w7 = (float)((c7 / s) * L10_2);

    const int tasks = planes * (HH / RPB);          // 2048
    dim3 grid(tasks / WARPS);                       // 512 blocks
    dim3 block(THREADS);
    holder_kernel<<<grid, block>>>(x, out, w3, w5, w7);
}